// round 3
// baseline (speedup 1.0000x reference)
#include <cuda_runtime.h>
#include <cstdint>

// CRF Viterbi decode: B=128, T=1024, K=128
// out[b,t,k] = one_hot(tags[b,t]) fp32

static constexpr int B_ = 128;
static constexpr int T_ = 1024;
static constexpr int K_ = 128;

// Shared memory layout (in 4-byte words)
static constexpr int TT_WORDS  = K_ * K_;            // 16384 raw row-major transitions
static constexpr int RMIN_OFF  = TT_WORDS;           // 16384
static constexpr int RMAX_OFF  = RMIN_OFF + K_;      // 16512
static constexpr int SS_OFF    = RMAX_OFF + K_;      // 16640 (state vector, 128 f32, 16B aligned)
static constexpr int TAGS_OFF  = SS_OFF + K_;        // 16768
static constexpr int BP_OFF    = TAGS_OFF + T_;      // 17792 (u32/(t,lane): 4 packed u8 backptrs)
static constexpr int SMEM_WORDS = BP_OFF + T_ * 32;  // 50560
static constexpr size_t SMEM_BYTES = (size_t)SMEM_WORDS * 4;  // 202240 B

// Monotone fp32 <-> ordered signed-int key (order-preserving bijection)
__device__ __forceinline__ int f2key(float x) {
    int i = __float_as_int(x);
    return i ^ ((i >> 31) & 0x7fffffff);
}
__device__ __forceinline__ float key2f(int k) {
    return __int_as_float(k ^ ((k >> 31) & 0x7fffffff));
}

__global__ void __launch_bounds__(128, 1)
viterbi_kernel(const float* __restrict__ logits,
               const int*   __restrict__ lens,
               const float* __restrict__ trans,
               float*       __restrict__ out)
{
    extern __shared__ float sm[];
    float*    Tt    = sm;
    float*    rminS = sm + RMIN_OFF;
    float*    rmaxS = sm + RMAX_OFF;
    float*    sS    = sm + SS_OFF;
    int*      tagsS = (int*)(sm + TAGS_OFF);
    unsigned* bpS   = (unsigned*)(sm + BP_OFF);

    const int b    = blockIdx.x;
    const int tid  = threadIdx.x;
    const int lane = tid & 31;
    const int warp = tid >> 5;

    int L = lens[b];
    L = L < 1 ? 1 : (L > T_ ? T_ : L);
    const float* lg = logits + (size_t)b * T_ * K_;

    // ---- Prologue: transitions -> smem, raw row-major (coalesced LDG.128/STS.128) ----
    {
        const float4* t4g = (const float4*)trans;
        float4*       d4  = (float4*)Tt;
        for (int i = tid; i < (K_ * K_) / 4; i += 128) d4[i] = t4g[i];
    }
    __syncthreads();

    // ---- Per-row min/max (thread = row; rotated float4 column order -> conflict-free) ----
    {
        const float4* rowp = (const float4*)(Tt + tid * K_);
        float mn = __int_as_float(0x7f800000);
        float mx = __int_as_float(0xff800000);
        #pragma unroll
        for (int c0 = 0; c0 < 32; ++c0) {
            int c = (c0 + tid) & 31;
            float4 v = rowp[c];
            mn = fminf(mn, fminf(fminf(v.x, v.y), fminf(v.z, v.w)));
            mx = fmaxf(mx, fmaxf(fmaxf(v.x, v.y), fmaxf(v.z, v.w)));
        }
        rminS[tid] = mn;
        rmaxS[tid] = mx;
    }
    __syncthreads();

    if (warp == 1) {
        // Warm L2 with this batch's logits ahead of warp 0's consumption.
        int nlines = L * (K_ / 32);  // 128B lines
        for (int i = lane; i < nlines; i += 32) {
            const float* p = lg + i * 32;
            asm volatile("prefetch.global.L2 [%0];" :: "l"(p));
        }
    }

    if (warp == 0) {
        // ---- Forward Viterbi: lane owns tags j = 4*lane + q, q = 0..3 ----
        const float4* lg4   = (const float4*)lg;   // index: t*32 + lane
        const float4* Trow4 = (const float4*)Tt;   // index: i*32 + lane

        float4 rmn4 = ((const float4*)rminS)[lane];
        float4 rmx4 = ((const float4*)rmaxS)[lane];
        float rmn[4] = {rmn4.x, rmn4.y, rmn4.z, rmn4.w};
        float rmx[4] = {rmx4.x, rmx4.y, rmx4.z, rmx4.w};

        float4 v0 = lg4[lane];                     // t=0 logits = init state
        float s[4] = {v0.x, v0.y, v0.z, v0.w};

        // depth-3 register pipeline of logits (rows t=1,2 always in-bounds: T=1024)
        float4 c1 = lg4[32 + lane];                // logit row t=1
        float4 c2 = lg4[64 + lane];                // logit row t=2

        // prefetch pointer for row t+2, advanced by one row per step (IADD only)
        const float4* pref     = lg4 + 96 + lane;             // row t=3 on first iter
        const float4* pref_end = lg4 + (T_ - 1) * 32 + lane;  // clamp: last valid row

        ((float4*)sS)[lane] = make_float4(s[0], s[1], s[2], s[3]);
        __syncwarp();

        for (int t = 1; t < L; ++t) {
            // prefetch logit row t+2 (pointer-clamped; value unused past end)
            float4 pn = *pref;
            pref = (pref < pref_end) ? (pref + 32) : pref_end;

            // LB key = max over tags of key(s + rowmin)  (exact, monotone)
            float l0 = s[0] + rmn[0];
            float l1 = s[1] + rmn[1];
            float l2 = s[2] + rmn[2];
            float l3 = s[3] + rmn[3];
            float lm  = fmaxf(fmaxf(l0, l1), fmaxf(l2, l3));
            int   kLB = __reduce_max_sync(0xffffffffu, f2key(lm));

            // candidate rows: key(s + rowmax) >= kLB  (contains every argmax winner, exactly)
            unsigned m0 = __ballot_sync(0xffffffffu, f2key(s[0] + rmx[0]) >= kLB);
            unsigned m1 = __ballot_sync(0xffffffffu, f2key(s[1] + rmx[1]) >= kLB);
            unsigned m2 = __ballot_sync(0xffffffffu, f2key(s[2] + rmx[2]) >= kLB);
            unsigned m3 = __ballot_sync(0xffffffffu, f2key(s[3] + rmx[3]) >= kLB);

            unsigned long long lo = (unsigned long long)m0 | ((unsigned long long)m1 << 32);
            unsigned long long hi = (unsigned long long)m2 | ((unsigned long long)m3 << 32);
            int cnt = __popcll(lo) + __popcll(hi);

            float best0, best1, best2, best3;
            unsigned bp;

            if (cnt == 1) {
                // single dominant predecessor: no compares needed
                int p = lo ? (__ffsll(lo) - 1) : (63 + __ffsll(hi));
                int q = p >> 5, cl = p & 31;
                int i = 4 * cl + q;
                float  sc = sS[i];                 // uniform-address LDS broadcast
                float4 tr = Trow4[i * 32 + lane];  // one LDS.128
                best0 = sc + tr.x; best1 = sc + tr.y;
                best2 = sc + tr.z; best3 = sc + tr.w;
                bp = (unsigned)i * 0x01010101u;
            } else {
                float b0 = __int_as_float(0xff800000), b1 = b0, b2 = b0, b3 = b0;
                int i0 = 0, i1 = 0, i2 = 0, i3 = 0;
                unsigned long long a = lo, h = hi;
                while (a | h) {
                    int p;
                    if (a) { p = __ffsll(a) - 1;  a &= a - 1; }
                    else   { p = 63 + __ffsll(h); h &= h - 1; }
                    int q = p >> 5, cl = p & 31;
                    int i = 4 * cl + q;
                    float  sc = sS[i];
                    float4 tr = Trow4[i * 32 + lane];
                    float w0 = sc + tr.x, w1 = sc + tr.y, w2 = sc + tr.z, w3 = sc + tr.w;
                    // exact first-index argmax in any enumeration order
                    bool g0 = (w0 > b0) || (w0 == b0 && i < i0);
                    bool g1 = (w1 > b1) || (w1 == b1 && i < i1);
                    bool g2 = (w2 > b2) || (w2 == b2 && i < i2);
                    bool g3 = (w3 > b3) || (w3 == b3 && i < i3);
                    b0 = g0 ? w0 : b0;  i0 = g0 ? i : i0;
                    b1 = g1 ? w1 : b1;  i1 = g1 ? i : i1;
                    b2 = g2 ? w2 : b2;  i2 = g2 ? i : i2;
                    b3 = g3 ? w3 : b3;  i3 = g3 ? i : i3;
                }
                best0 = b0; best1 = b1; best2 = b2; best3 = b3;
                bp = (unsigned)i0 | ((unsigned)i1 << 8) |
                     ((unsigned)i2 << 16) | ((unsigned)i3 << 24);
            }

            s[0] = best0 + c1.x;
            s[1] = best1 + c1.y;
            s[2] = best2 + c1.z;
            s[3] = best3 + c1.w;

            ((float4*)sS)[lane] = make_float4(s[0], s[1], s[2], s[3]);
            bpS[t * 32 + lane] = bp;
            __syncwarp();

            c1 = c2; c2 = pn;
        }

        // ---- last_tag = first argmax of final state ----
        float fm = fmaxf(fmaxf(s[0], s[1]), fmaxf(s[2], s[3]));
        int   mk = __reduce_max_sync(0xffffffffu, f2key(fm));
        float M  = key2f(mk);
        unsigned cand = 0x7fffffffu;
        #pragma unroll
        for (int q = 0; q < 4; ++q) {
            unsigned tg = (unsigned)(4 * lane + q);
            cand = (s[q] == M && tg < cand) ? tg : cand;
        }
        int last = (int)__reduce_min_sync(0xffffffffu, cand);

        // tags[t] = last for t in [L-1, T)  (bp is identity past L)
        for (int t = L - 1 + lane; t < T_; t += 32) tagsS[t] = last;

        // ---- backtrack (lane 0; dependent LDS chain over smem bp) ----
        if (lane == 0) {
            int cur = last;
            for (int t = L - 1; t >= 1; --t) {
                unsigned w = bpS[t * 32 + (cur >> 2)];
                cur = (int)((w >> ((cur & 3) * 8)) & 0xffu);
                tagsS[t - 1] = cur;
            }
        }
    }
    __syncthreads();

    // ---- one-hot epilogue: 512 KB per CTA, coalesced STG.128 ----
    float4* out4 = (float4*)(out + (size_t)b * T_ * K_);
    for (int idx = tid; idx < T_ * (K_ / 4); idx += 128) {
        int t = idx >> 5;
        int c = (idx & 31) * 4;
        int tag = tagsS[t];
        float4 v;
        v.x = (tag == c    ) ? 1.f : 0.f;
        v.y = (tag == c + 1) ? 1.f : 0.f;
        v.z = (tag == c + 2) ? 1.f : 0.f;
        v.w = (tag == c + 3) ? 1.f : 0.f;
        out4[idx] = v;
    }
}

extern "C" void kernel_launch(void* const* d_in, const int* in_sizes, int n_in,
                              void* d_out, int out_size)
{
    const float* logits = (const float*)d_in[0];
    const int*   lens   = (const int*)d_in[1];
    const float* trans  = (const float*)d_in[2];
    float*       out    = (float*)d_out;

    cudaFuncSetAttribute(viterbi_kernel,
                         cudaFuncAttributeMaxDynamicSharedMemorySize,
                         (int)SMEM_BYTES);
    viterbi_kernel<<<B_, 128, SMEM_BYTES>>>(logits, lens, trans, out);
}

// round 4
// speedup vs baseline: 1.9317x; 1.9317x over previous
#include <cuda_runtime.h>
#include <cstdint>

// CRF Viterbi decode: B=128, T=1024, K=128
// out[b,t,k] = one_hot(tags[b,t]) fp32
//
// Design: 1 CTA/batch. Warp 0 runs the serial Viterbi recurrence with
// provably-exact candidate pruning; warps 1-3 stage the logit stream into a
// double-buffered smem ring so the serial chain never touches DRAM latency.

static constexpr int B_ = 128;
static constexpr int T_ = 1024;
static constexpr int K_ = 128;
static constexpr int CHUNK = 16;                      // rows per ring buffer

// Shared memory layout (in 4-byte words)
static constexpr int TT_WORDS  = K_ * K_;             // 16384 row-major transitions
static constexpr int RMIN_OFF  = TT_WORDS;            // 16384
static constexpr int RMAX_OFF  = RMIN_OFF + K_;       // 16512
static constexpr int SS_OFF    = RMAX_OFF + K_;       // 16640 (state vector)
static constexpr int TAGS_OFF  = SS_OFF + K_;         // 16768
static constexpr int BP_OFF    = TAGS_OFF + T_;       // 17792 (u32/(t,lane): 4 packed u8 bp)
static constexpr int RING_OFF  = BP_OFF + T_ * 32;    // 50560 (2 x CHUNK x 128 floats)
static constexpr int SMEM_WORDS = RING_OFF + 2 * CHUNK * K_;  // 54656
static constexpr size_t SMEM_BYTES = (size_t)SMEM_WORDS * 4;  // 218624 B

// Monotone fp32 <-> ordered signed-int key (order-preserving bijection)
__device__ __forceinline__ int f2key(float x) {
    int i = __float_as_int(x);
    return i ^ ((i >> 31) & 0x7fffffff);
}
__device__ __forceinline__ float key2f(int k) {
    return __int_as_float(k ^ ((k >> 31) & 0x7fffffff));
}

__global__ void __launch_bounds__(128, 1)
viterbi_kernel(const float* __restrict__ logits,
               const int*   __restrict__ lens,
               const float* __restrict__ trans,
               float*       __restrict__ out)
{
    extern __shared__ float sm[];
    float*    Tt    = sm;
    float*    rminS = sm + RMIN_OFF;
    float*    rmaxS = sm + RMAX_OFF;
    float*    sS    = sm + SS_OFF;
    int*      tagsS = (int*)(sm + TAGS_OFF);
    unsigned* bpS   = (unsigned*)(sm + BP_OFF);
    float4*   ring4 = (float4*)(sm + RING_OFF);       // [2][CHUNK][32] float4

    const int b    = blockIdx.x;
    const int tid  = threadIdx.x;
    const int lane = tid & 31;
    const int warp = tid >> 5;

    int L = lens[b];
    L = L < 1 ? 1 : (L > T_ ? T_ : L);
    const float*  lg  = logits + (size_t)b * T_ * K_;
    const float4* lg4 = (const float4*)lg;            // index: t*32 + c

    // ---- Prologue: transitions -> smem, row-major (coalesced LDG.128/STS.128) ----
    {
        const float4* t4g = (const float4*)trans;
        float4*       d4  = (float4*)Tt;
        for (int i = tid; i < (K_ * K_) / 4; i += 128) d4[i] = t4g[i];
    }
    __syncthreads();

    // ---- Per-row min/max (thread = row; rotated column order -> conflict-free) ----
    {
        const float4* rowp = (const float4*)(Tt + tid * K_);
        float mn = __int_as_float(0x7f800000);
        float mx = __int_as_float(0xff800000);
        #pragma unroll
        for (int c0 = 0; c0 < 32; ++c0) {
            int c = (c0 + tid) & 31;
            float4 v = rowp[c];
            mn = fminf(mn, fminf(fminf(v.x, v.y), fminf(v.z, v.w)));
            mx = fmaxf(mx, fmaxf(fmaxf(v.x, v.y), fmaxf(v.z, v.w)));
        }
        rminS[tid] = mn;
        rmaxS[tid] = mx;
    }

    // ---- Prefill ring buffer 0 with logit rows [1, 1+CHUNK) (producers) ----
    if (warp != 0) {
        int ptid = tid - 32;                          // 0..95
        for (int i = ptid; i < CHUNK * 32; i += 96) {
            int r = 1 + (i >> 5); r = r < T_ ? r : T_ - 1;
            ring4[i] = lg4[r * 32 + (i & 31)];
        }
    }
    __syncthreads();

    // Persistent per-warp0 registers (declared outside so post-loop code sees them)
    float s[4];
    float rmn[4], rmx[4];
    if (warp == 0) {
        float4 rmn4 = ((const float4*)rminS)[lane];
        float4 rmx4 = ((const float4*)rmaxS)[lane];
        rmn[0]=rmn4.x; rmn[1]=rmn4.y; rmn[2]=rmn4.z; rmn[3]=rmn4.w;
        rmx[0]=rmx4.x; rmx[1]=rmx4.y; rmx[2]=rmx4.z; rmx[3]=rmx4.w;
        float4 v0 = lg4[lane];                        // t=0 logits = init state
        s[0]=v0.x; s[1]=v0.y; s[2]=v0.z; s[3]=v0.w;
        ((float4*)sS)[lane] = v0;
        __syncwarp();
    }

    const float4* Trow4 = (const float4*)Tt;          // index: i*32 + lane

    // ---- Chunked forward loop: producers stage chunk ci+1 while warp 0 eats ci ----
    const int nchunks = (L + CHUNK - 2) / CHUNK;      // ceil((L-1)/CHUNK)
    for (int ci = 0; ci < nchunks; ++ci) {
        const int base = 1 + ci * CHUNK;

        if (warp != 0) {
            // stage logit rows [base+CHUNK, base+2*CHUNK) into the other buffer
            int ptid = tid - 32;
            float4* dst = ring4 + ((ci + 1) & 1) * (CHUNK * 32);
            int nb = base + CHUNK;
            #pragma unroll 2
            for (int i = ptid; i < CHUNK * 32; i += 96) {
                int r = nb + (i >> 5); r = r < T_ ? r : T_ - 1;
                dst[i] = lg4[r * 32 + (i & 31)];
            }
        } else {
            const float4* src = ring4 + (ci & 1) * (CHUNK * 32);
            int tend = base + CHUNK < L ? base + CHUNK : L;
            for (int t = base; t < tend; ++t) {
                // logit row t from smem ring (latency hidden under the chain below)
                float4 cl = src[(t - base) * 32 + lane];

                // LB key = max over tags of key(s + rowmin)  (exact, monotone)
                float l0 = s[0] + rmn[0];
                float l1 = s[1] + rmn[1];
                float l2 = s[2] + rmn[2];
                float l3 = s[3] + rmn[3];
                float lm  = fmaxf(fmaxf(l0, l1), fmaxf(l2, l3));
                int   kLB = __reduce_max_sync(0xffffffffu, f2key(lm));

                // candidate rows: key(s + rowmax) >= kLB (contains every argmax winner)
                unsigned m0 = __ballot_sync(0xffffffffu, f2key(s[0] + rmx[0]) >= kLB);
                unsigned m1 = __ballot_sync(0xffffffffu, f2key(s[1] + rmx[1]) >= kLB);
                unsigned m2 = __ballot_sync(0xffffffffu, f2key(s[2] + rmx[2]) >= kLB);
                unsigned m3 = __ballot_sync(0xffffffffu, f2key(s[3] + rmx[3]) >= kLB);

                unsigned long long a = (unsigned long long)m0 | ((unsigned long long)m1 << 32);
                unsigned long long h = (unsigned long long)m2 | ((unsigned long long)m3 << 32);

                float b0 = __int_as_float(0xff800000), b1 = b0, b2 = b0, b3 = b0;
                int i0 = 0, i1 = 0, i2 = 0, i3 = 0;
                while (a | h) {
                    int p;
                    if (a) { p = __ffsll(a) - 1;  a &= a - 1; }
                    else   { p = 63 + __ffsll(h); h &= h - 1; }
                    int q = p >> 5, cl_ = p & 31;
                    int i = 4 * cl_ + q;
                    float  sc = sS[i];                 // uniform-address LDS broadcast
                    float4 tr = Trow4[i * 32 + lane];  // one LDS.128
                    float w0 = sc + tr.x, w1 = sc + tr.y, w2 = sc + tr.z, w3 = sc + tr.w;
                    // exact first-index argmax in any enumeration order
                    bool g0 = (w0 > b0) || (w0 == b0 && i < i0);
                    bool g1 = (w1 > b1) || (w1 == b1 && i < i1);
                    bool g2 = (w2 > b2) || (w2 == b2 && i < i2);
                    bool g3 = (w3 > b3) || (w3 == b3 && i < i3);
                    b0 = g0 ? w0 : b0;  i0 = g0 ? i : i0;
                    b1 = g1 ? w1 : b1;  i1 = g1 ? i : i1;
                    b2 = g2 ? w2 : b2;  i2 = g2 ? i : i2;
                    b3 = g3 ? w3 : b3;  i3 = g3 ? i : i3;
                }

                s[0] = b0 + cl.x;
                s[1] = b1 + cl.y;
                s[2] = b2 + cl.z;
                s[3] = b3 + cl.w;

                ((float4*)sS)[lane] = make_float4(s[0], s[1], s[2], s[3]);
                bpS[t * 32 + lane] = (unsigned)i0 | ((unsigned)i1 << 8) |
                                     ((unsigned)i2 << 16) | ((unsigned)i3 << 24);
                __syncwarp();
            }
        }
        __syncthreads();   // chunk handoff: ring slot (ci+1) full, slot ci free
    }

    if (warp == 0) {
        // ---- last_tag = first argmax of final state ----
        float fm = fmaxf(fmaxf(s[0], s[1]), fmaxf(s[2], s[3]));
        int   mk = __reduce_max_sync(0xffffffffu, f2key(fm));
        float M  = key2f(mk);
        unsigned cand = 0x7fffffffu;
        #pragma unroll
        for (int q = 0; q < 4; ++q) {
            unsigned tg = (unsigned)(4 * lane + q);
            cand = (s[q] == M && tg < cand) ? tg : cand;
        }
        int last = (int)__reduce_min_sync(0xffffffffu, cand);

        // tags[t] = last for t in [L-1, T)  (bp is identity past L)
        for (int t = L - 1 + lane; t < T_; t += 32) tagsS[t] = last;

        // ---- backtrack (lane 0; dependent LDS chain over smem bp) ----
        if (lane == 0) {
            int cur = last;
            for (int t = L - 1; t >= 1; --t) {
                unsigned w = bpS[t * 32 + (cur >> 2)];
                cur = (int)((w >> ((cur & 3) * 8)) & 0xffu);
                tagsS[t - 1] = cur;
            }
        }
    }
    __syncthreads();

    // ---- one-hot epilogue: 512 KB per CTA, coalesced STG.128 ----
    float4* out4 = (float4*)(out + (size_t)b * T_ * K_);
    for (int idx = tid; idx < T_ * (K_ / 4); idx += 128) {
        int t = idx >> 5;
        int c = (idx & 31) * 4;
        int tag = tagsS[t];
        float4 v;
        v.x = (tag == c    ) ? 1.f : 0.f;
        v.y = (tag == c + 1) ? 1.f : 0.f;
        v.z = (tag == c + 2) ? 1.f : 0.f;
        v.w = (tag == c + 3) ? 1.f : 0.f;
        out4[idx] = v;
    }
}

extern "C" void kernel_launch(void* const* d_in, const int* in_sizes, int n_in,
                              void* d_out, int out_size)
{
    const float* logits = (const float*)d_in[0];
    const int*   lens   = (const int*)d_in[1];
    const float* trans  = (const float*)d_in[2];
    float*       out    = (float*)d_out;

    cudaFuncSetAttribute(viterbi_kernel,
                         cudaFuncAttributeMaxDynamicSharedMemorySize,
                         (int)SMEM_BYTES);
    viterbi_kernel<<<B_, 128, SMEM_BYTES>>>(logits, lens, trans, out);
}